// round 1
// baseline (speedup 1.0000x reference)
#include <cuda_runtime.h>
#include <math.h>

#define B_    32
#define NIN   1024
#define NHID  2048
#define NOUT  512
#define TT    256
#define KLEN  62          // truncated alpha kernel length (indices 0..61), tau=8
#define THETA 10.0f

// ---------------- scratch (alloc-free: __device__ globals) ----------------
__device__ float g_srm[64];
__device__ float g_ref[64];

__device__ float g_xt[(size_t)B_ * TT * NIN];   // 32 MB  x transposed [b][t][i]
__device__ float g_a1[(size_t)B_ * TT * NHID];  // 64 MB  fc1 out      [b][t][h]
__device__ float g_u1[(size_t)B_ * TT * NHID];  // 64 MB  psp1 / s1    [b][t][h]
__device__ float g_a2[(size_t)B_ * TT * NOUT];  // 16 MB  fc2 out      [b][t][o]
__device__ float g_u2[(size_t)B_ * TT * NOUT];  // 16 MB  psp2         [b][t][o]

// ---------------- kernel tables (match reference double-precision math) ----
__global__ void init_tables() {
    int k = threadIdx.x;
    if (k < 64) {
        double v = 0.0;
        if (k < KLEN) {
            double t = (double)k;
            v = (t / 8.0) * exp(1.0 - t / 8.0);   // alpha(t), peak 1 at t=tau
        }
        g_srm[k] = (float)v;            // mult = 1
        g_ref[k] = (float)(-20.0 * v);  // mult = -scaleRef*theta = -20
    }
}

// ---------------- transpose x[b][i][t] -> xt[b][t][i] ----------------------
__global__ __launch_bounds__(256) void transpose_xt(const float* __restrict__ x,
                                                    float* __restrict__ xt) {
    __shared__ float tile[32][33];
    int b  = blockIdx.z;
    int i0 = blockIdx.y * 32;
    int t0 = blockIdx.x * 32;
    for (int r = threadIdx.y; r < 32; r += 8)
        tile[r][threadIdx.x] = x[((size_t)b * NIN + i0 + r) * TT + t0 + threadIdx.x];
    __syncthreads();
    for (int r = threadIdx.y; r < 32; r += 8)
        xt[((size_t)b * TT + t0 + r) * NIN + i0 + threadIdx.x] = tile[threadIdx.x][r];
}

// ---------------- batched NT GEMM: C[b][m][n] = sum_k A[b][m][k] * W[n][k] --
// A: per-batch (M x K) row-major, W: (N x K) row-major shared across batch.
// Block 64x64, BK=16, 256 threads, 4x4 micro-tile.
__global__ __launch_bounds__(256) void gemm_nt(const float* __restrict__ A,
                                               const float* __restrict__ W,
                                               float* __restrict__ C,
                                               int M, int N, int K) {
    __shared__ float As[16][68];
    __shared__ float Ws[16][68];

    int b  = blockIdx.z;
    const float* Ab = A + (size_t)b * M * K;
    float*       Cb = C + (size_t)b * M * N;
    int m0 = blockIdx.y * 64;
    int n0 = blockIdx.x * 64;

    int tid  = threadIdx.x;
    int tm   = tid >> 4;          // 0..15
    int tn   = tid & 15;          // 0..15
    int lrow = tid >> 2;          // 0..63
    int lk4  = (tid & 3) * 4;     // 0,4,8,12

    float acc[4][4];
#pragma unroll
    for (int i = 0; i < 4; i++)
#pragma unroll
        for (int j = 0; j < 4; j++) acc[i][j] = 0.0f;

    for (int k0 = 0; k0 < K; k0 += 16) {
        float4 a4 = *(const float4*)(Ab + (size_t)(m0 + lrow) * K + k0 + lk4);
        float4 w4 = *(const float4*)(W  + (size_t)(n0 + lrow) * K + k0 + lk4);
        As[lk4 + 0][lrow] = a4.x; As[lk4 + 1][lrow] = a4.y;
        As[lk4 + 2][lrow] = a4.z; As[lk4 + 3][lrow] = a4.w;
        Ws[lk4 + 0][lrow] = w4.x; Ws[lk4 + 1][lrow] = w4.y;
        Ws[lk4 + 2][lrow] = w4.z; Ws[lk4 + 3][lrow] = w4.w;
        __syncthreads();
#pragma unroll
        for (int k = 0; k < 16; k++) {
            float4 ar = *(const float4*)&As[k][tm * 4];
            float4 wr = *(const float4*)&Ws[k][tn * 4];
            float am[4] = {ar.x, ar.y, ar.z, ar.w};
            float wn[4] = {wr.x, wr.y, wr.z, wr.w};
#pragma unroll
            for (int i = 0; i < 4; i++)
#pragma unroll
                for (int j = 0; j < 4; j++) acc[i][j] += am[i] * wn[j];
        }
        __syncthreads();
    }
#pragma unroll
    for (int i = 0; i < 4; i++) {
        float4 v = make_float4(acc[i][0], acc[i][1], acc[i][2], acc[i][3]);
        *(float4*)(Cb + (size_t)(m0 + tm * 4 + i) * N + n0 + tn * 4) = v;
    }
}

// ---------------- causal PSP conv along t, layout [b][t][c] -----------------
// out[b,t,c] = sum_{k=1..min(61,t)} srm[k] * in[b,t-k,c]   (srm[0]=0)
__global__ __launch_bounds__(256) void psp_kernel(const float* __restrict__ in,
                                                  float* __restrict__ out, int C) {
    __shared__ float tile[TT][33];
    __shared__ float srm[64];
    int b  = blockIdx.y;
    int c0 = blockIdx.x * 32;
    int tid = threadIdx.x;
    if (tid < 64) srm[tid] = g_srm[tid];

    const float* pin = in + (size_t)b * TT * C + c0;
    for (int idx = tid; idx < TT * 32; idx += 256) {
        int t = idx >> 5, c = idx & 31;
        tile[t][c] = pin[(size_t)t * C + c];
    }
    __syncthreads();

    float* pout = out + (size_t)b * TT * C + c0;
    for (int idx = tid; idx < TT * 32; idx += 256) {
        int t = idx >> 5, c = idx & 31;
        float acc = 0.0f;
        int kmax = min(KLEN - 1, t);
        for (int k = 1; k <= kmax; k++)
            acc += srm[k] * tile[t - k][c];
        pout[(size_t)t * C + c] = acc;
    }
}

// ---------------- threshold + refractory scan ------------------------------
// One thread per (b, c). Spike history kept as a 61-bit mask; refractory
// contribution = sum over set bits of ref[age] (exactly the truncated kernel,
// ref[0]=0 so same-step spikes excluded — matches the reference scan).
__global__ __launch_bounds__(256) void scan_kernel(const float* upsp,
                                                   float* sout,
                                                   int C, int tmajor_out) {
    __shared__ float ref[64];
    if (threadIdx.x < 64) ref[threadIdx.x] = g_ref[threadIdx.x];
    __syncthreads();

    int idx = blockIdx.x * blockDim.x + threadIdx.x;
    if (idx >= B_ * C) return;
    int b = idx / C, c = idx % C;

    const float* up = upsp + (size_t)b * TT * C + c;
    unsigned long long mask = 0ull;
    const unsigned long long M61 = (1ull << 61) - 1ull;

    for (int t = 0; t < TT; t++) {
        float u = up[(size_t)t * C];
        unsigned long long m = mask;
        while (m) {
            int j = __ffsll((long long)m) - 1;   // age = j+1
            u += ref[j + 1];
            m &= m - 1;
        }
        unsigned long long s = (u >= THETA) ? 1ull : 0ull;
        float sf = (float)s;
        mask = ((mask << 1) | s) & M61;
        if (tmajor_out)
            sout[((size_t)b * C + c) * TT + t] = sf;   // output layout (b, o, t)
        else
            sout[((size_t)b * TT + t) * C + c] = sf;   // in-place [b][t][c]
    }
}

// ---------------- launch ----------------------------------------------------
extern "C" void kernel_launch(void* const* d_in, const int* in_sizes, int n_in,
                              void* d_out, int out_size) {
    const float* x  = (const float*)d_in[0];   // (32, 1024, 256)
    const float* w1 = (const float*)d_in[1];   // (2048, 1024)
    const float* w2 = (const float*)d_in[2];   // (512, 2048)
    float* out = (float*)d_out;                // (32, 512, 256)

    float *xt, *a1, *u1, *a2, *u2;
    cudaGetSymbolAddress((void**)&xt, g_xt);
    cudaGetSymbolAddress((void**)&a1, g_a1);
    cudaGetSymbolAddress((void**)&u1, g_u1);
    cudaGetSymbolAddress((void**)&a2, g_a2);
    cudaGetSymbolAddress((void**)&u2, g_u2);

    init_tables<<<1, 64>>>();

    // x[b][i][t] -> xt[b][t][i]
    transpose_xt<<<dim3(TT / 32, NIN / 32, B_), dim3(32, 8)>>>(x, xt);

    // fc1: a1[b][t][h] = sum_i xt[b][t][i] * w1[h][i]
    gemm_nt<<<dim3(NHID / 64, TT / 64, B_), 256>>>(xt, w1, a1, TT, NHID, NIN);

    // psp1
    psp_kernel<<<dim3(NHID / 32, B_), 256>>>(a1, u1, NHID);

    // spike scan 1 (in-place: s1 overwrites u1)
    scan_kernel<<<(B_ * NHID + 255) / 256, 256>>>(u1, u1, NHID, 0);

    // fc2: a2[b][t][o] = sum_h s1[b][t][h] * w2[o][h]
    gemm_nt<<<dim3(NOUT / 64, TT / 64, B_), 256>>>(u1, w2, a2, TT, NOUT, NHID);

    // psp2
    psp_kernel<<<dim3(NOUT / 32, B_), 256>>>(a2, u2, NOUT);

    // spike scan 2 -> d_out in (b, o, t) layout
    scan_kernel<<<(B_ * NOUT + 255) / 256, 256>>>(u2, out, NOUT, 1);
}

// round 2
// speedup vs baseline: 1.2910x; 1.2910x over previous
#include <cuda_runtime.h>
#include <math.h>

#define B_    32
#define NIN   1024
#define NHID  2048
#define NOUT  512
#define TT    256
#define KLEN  62          // truncated alpha kernel length (indices 0..61), tau=8
#define THETA 10.0f

// ---------------- scratch (alloc-free: __device__ globals) ----------------
__device__ float g_srm[64];
__device__ float g_ref[64];

__device__ float g_a1[(size_t)B_ * TT * NHID];  // 64 MB  fc1 out  [b][t][h]
__device__ float g_s1[(size_t)B_ * TT * NHID];  // 64 MB  spikes1  [b][t][h]
__device__ float g_a2[(size_t)B_ * TT * NOUT];  // 16 MB  fc2 out  [b][t][o]

// ---------------- kernel tables (match reference double-precision math) ----
__global__ void init_tables() {
    int k = threadIdx.x;
    if (k < 64) {
        double v = 0.0;
        if (k < KLEN) {
            double t = (double)k;
            v = (t / 8.0) * exp(1.0 - t / 8.0);   // alpha(t), peak 1 at t=tau
        }
        g_srm[k] = (float)v;            // mult = 1
        g_ref[k] = (float)(-20.0 * v);  // mult = -scaleRef*theta = -20
    }
}

// ---------------- 128x128x8 double-buffered SGEMM, 8x8 microtile -----------
// C[b][m][n] = sum_k A_logical[b][m][k] * W[n][k]
//   TRANSA=false: A row-major (M x K) per batch (A_logical = A)
//   TRANSA=true : A stored as x[b][k][m] (k-major rows, m contiguous) — the
//                 input spike tensor [b][i][t]; loader transposes on the fly.
#define BM 128
#define BN 128
#define BKG 8
#define PADG 132   // smem row stride in floats (128 + 4)

template <bool TRANSA>
__global__ __launch_bounds__(256) void gemm128(const float* __restrict__ A,
                                               const float* __restrict__ W,
                                               float* __restrict__ C,
                                               int M, int N, int K) {
    __shared__ float As[2][BKG][PADG];
    __shared__ float Ws[2][BKG][PADG];

    int b = blockIdx.z;
    const float* Ab = A + (TRANSA ? (size_t)b * K * M : (size_t)b * M * K);
    float*       Cb = C + (size_t)b * M * N;
    int m0 = blockIdx.y * BM;
    int n0 = blockIdx.x * BN;

    int tid  = threadIdx.x;
    int lane = tid & 31;
    int warp = tid >> 5;
    int m_off = (warp >> 1) * 32 + (lane >> 3) * 4;   // rows: m_off..+3, m_off+16..+19
    int n_off = (warp & 1) * 64 + (lane & 7) * 4;     // cols: n_off..+3, n_off+32..+35

    // loader indices
    int a_tk  = tid >> 5;          // TRANSA: k-row within tile (0..7)
    int a_tm  = (tid & 31) * 4;    // TRANSA: m offset (contiguous float4)
    int r_row = tid >> 1;          // normal A / W: tile row (0..127)
    int r_k4  = (tid & 1) * 4;     // normal A / W: k offset (0 or 4)

    float acc[8][8];
#pragma unroll
    for (int i = 0; i < 8; i++)
#pragma unroll
        for (int j = 0; j < 8; j++) acc[i][j] = 0.0f;

    // ---- prologue: stage 0 directly into smem ----
    {
        if (TRANSA) {
            float4 ra = *(const float4*)(Ab + (size_t)a_tk * M + m0 + a_tm);
            *(float4*)&As[0][a_tk][a_tm] = ra;
        } else {
            float4 ra = *(const float4*)(Ab + (size_t)(m0 + r_row) * K + r_k4);
            As[0][r_k4 + 0][r_row] = ra.x; As[0][r_k4 + 1][r_row] = ra.y;
            As[0][r_k4 + 2][r_row] = ra.z; As[0][r_k4 + 3][r_row] = ra.w;
        }
        float4 rb = *(const float4*)(W + (size_t)(n0 + r_row) * K + r_k4);
        Ws[0][r_k4 + 0][r_row] = rb.x; Ws[0][r_k4 + 1][r_row] = rb.y;
        Ws[0][r_k4 + 2][r_row] = rb.z; Ws[0][r_k4 + 3][r_row] = rb.w;
    }
    __syncthreads();

    int buf = 0;
    for (int k0 = BKG; k0 < K + BKG; k0 += BKG) {
        bool more = (k0 < K);
        float4 ra, rb;
        if (more) {
            if (TRANSA)
                ra = *(const float4*)(Ab + (size_t)(k0 + a_tk) * M + m0 + a_tm);
            else
                ra = *(const float4*)(Ab + (size_t)(m0 + r_row) * K + k0 + r_k4);
            rb = *(const float4*)(W + (size_t)(n0 + r_row) * K + k0 + r_k4);
        }

#pragma unroll
        for (int k = 0; k < BKG; k++) {
            float4 a0 = *(const float4*)&As[buf][k][m_off];
            float4 a1 = *(const float4*)&As[buf][k][m_off + 16];
            float4 b0 = *(const float4*)&Ws[buf][k][n_off];
            float4 b1 = *(const float4*)&Ws[buf][k][n_off + 32];
            float am[8] = {a0.x, a0.y, a0.z, a0.w, a1.x, a1.y, a1.z, a1.w};
            float bn[8] = {b0.x, b0.y, b0.z, b0.w, b1.x, b1.y, b1.z, b1.w};
#pragma unroll
            for (int i = 0; i < 8; i++)
#pragma unroll
                for (int j = 0; j < 8; j++) acc[i][j] += am[i] * bn[j];
        }

        if (more) {
            __syncthreads();
            int nb = buf ^ 1;
            if (TRANSA) {
                *(float4*)&As[nb][a_tk][a_tm] = ra;
            } else {
                As[nb][r_k4 + 0][r_row] = ra.x; As[nb][r_k4 + 1][r_row] = ra.y;
                As[nb][r_k4 + 2][r_row] = ra.z; As[nb][r_k4 + 3][r_row] = ra.w;
            }
            Ws[nb][r_k4 + 0][r_row] = rb.x; Ws[nb][r_k4 + 1][r_row] = rb.y;
            Ws[nb][r_k4 + 2][r_row] = rb.z; Ws[nb][r_k4 + 3][r_row] = rb.w;
            __syncthreads();
            buf = nb;
        }
    }

#pragma unroll
    for (int i = 0; i < 8; i++) {
        int m = m0 + m_off + ((i < 4) ? i : 12 + i);   // i>=4 -> +16+(i-4)
        float4 v0 = make_float4(acc[i][0], acc[i][1], acc[i][2], acc[i][3]);
        float4 v1 = make_float4(acc[i][4], acc[i][5], acc[i][6], acc[i][7]);
        *(float4*)(Cb + (size_t)m * N + n0 + n_off)      = v0;
        *(float4*)(Cb + (size_t)m * N + n0 + n_off + 32) = v1;
    }
}

// ---------------- fused PSP conv + threshold/refractory scan ---------------
// Block: 32 channels x full time axis. PSP via register sliding window
// (16 outputs/thread); then the scan runs on the u values in shared memory;
// spikes written to gmem ([b][t][c] for layer 1, [b][c][t] staged through
// shared for the t-major final output).
template <bool TMAJOR>
__global__ __launch_bounds__(256) void psp_scan(const float* __restrict__ in,
                                                float* __restrict__ sout, int C) {
    __shared__ float tile[TT + 61][33];   // rows 0..60 = zero pad (causal past)
    __shared__ float srm[64];
    __shared__ float ref[64];

    int b  = blockIdx.y;
    int c0 = blockIdx.x * 32;
    int tid = threadIdx.x;

    if (tid < 64)       srm[tid] = g_srm[tid];
    else if (tid < 128) ref[tid - 64] = g_ref[tid - 64];

    for (int idx = tid; idx < 61 * 32; idx += 256)
        tile[idx >> 5][idx & 31] = 0.0f;

    const float* pin = in + (size_t)b * TT * C + c0;
    for (int idx = tid; idx < TT * 32; idx += 256) {
        int t = idx >> 5, c = idx & 31;
        tile[61 + t][c] = pin[(size_t)t * C + c];
    }
    __syncthreads();

    // ---- PSP: 512 work items = 32 channels x 16 chunks of 16 timesteps ----
    float acc[2][16];
    int cc[2], tt0[2];
#pragma unroll
    for (int j = 0; j < 2; j++) {
        int item = tid + 256 * j;
        int c  = item & 31;
        int t0 = (item >> 5) * 16;
        cc[j] = c; tt0[j] = t0;

        float w[16];
#pragma unroll
        for (int i = 0; i < 16; i++) w[i] = tile[61 + t0 - 1 + i][c];  // k=1 window
#pragma unroll
        for (int i = 0; i < 16; i++) acc[j][i] = 0.0f;

#pragma unroll
        for (int k = 1; k < KLEN; k++) {
            float s = srm[k];
#pragma unroll
            for (int i = 0; i < 16; i++) acc[j][i] += s * w[i];
            if (k < KLEN - 1) {
#pragma unroll
                for (int i = 15; i > 0; i--) w[i] = w[i - 1];
                w[0] = tile[61 + t0 - (k + 1)][c];
            }
        }
    }
    __syncthreads();

    // write u back into the tile (inputs fully consumed)
#pragma unroll
    for (int j = 0; j < 2; j++)
#pragma unroll
        for (int i = 0; i < 16; i++)
            tile[61 + tt0[j] + i][cc[j]] = acc[j][i];
    __syncthreads();

    // ---- scan: one thread per channel, 61-bit spike-history mask ----
    if (tid < 32) {
        int c = tid;
        unsigned long long mask = 0ull;
        const unsigned long long M61 = (1ull << 61) - 1ull;
        for (int t = 0; t < TT; t++) {
            float u = tile[61 + t][c];
            unsigned long long m = mask;
            while (m) {
                int j = __ffsll((long long)m) - 1;   // age = j+1
                u += ref[j + 1];
                m &= m - 1;
            }
            unsigned long long s = (u >= THETA) ? 1ull : 0ull;
            float sf = (float)s;
            mask = ((mask << 1) | s) & M61;
            if (TMAJOR)
                tile[61 + t][c] = sf;                         // stage for coalesced write
            else
                sout[((size_t)b * TT + t) * C + c0 + c] = sf; // [b][t][c], coalesced
        }
    }

    if (TMAJOR) {
        __syncthreads();
        for (int idx = tid; idx < TT * 32; idx += 256) {
            int t = idx & 255, c = idx >> 8;                  // t-fast: coalesced STG
            sout[((size_t)b * C + c0 + c) * TT + t] = tile[61 + t][c];
        }
    }
}

// ---------------- launch ----------------------------------------------------
extern "C" void kernel_launch(void* const* d_in, const int* in_sizes, int n_in,
                              void* d_out, int out_size) {
    const float* x  = (const float*)d_in[0];   // (32, 1024, 256)
    const float* w1 = (const float*)d_in[1];   // (2048, 1024)
    const float* w2 = (const float*)d_in[2];   // (512, 2048)
    float* out = (float*)d_out;                // (32, 512, 256)

    float *a1, *s1, *a2;
    cudaGetSymbolAddress((void**)&a1, g_a1);
    cudaGetSymbolAddress((void**)&s1, g_s1);
    cudaGetSymbolAddress((void**)&a2, g_a2);

    init_tables<<<1, 64>>>();

    // fc1: a1[b][t][h] = sum_i x[b][i][t] * w1[h][i]   (A transposed on load)
    gemm128<true><<<dim3(NHID / BN, TT / BM, B_), 256>>>(x, w1, a1, TT, NHID, NIN);

    // psp1 + scan1 -> spikes s1 [b][t][h]
    psp_scan<false><<<dim3(NHID / 32, B_), 256>>>(a1, s1, NHID);

    // fc2: a2[b][t][o] = sum_h s1[b][t][h] * w2[o][h]
    gemm128<false><<<dim3(NOUT / BN, TT / BM, B_), 256>>>(s1, w2, a2, TT, NOUT, NHID);

    // psp2 + scan2 -> d_out in (b, o, t) layout
    psp_scan<true><<<dim3(NOUT / 32, B_), 256>>>(a2, out, NOUT);
}